// round 8
// baseline (speedup 1.0000x reference)
#include <cuda_runtime.h>

#define EMBED   1024
#define EPB     8
#define NB      64
#define KTOP    2
#define SPLIT   8
#define CAP     2048   // worst-case tokens per (bucket,slice) block

__device__ float g_key_rnorm[NB * EPB];
__device__ int   g_is64;

// ---------------------------------------------------------------------------
// Kernel D: detect op_id element width. If int64 (LE), every odd-indexed
// 32-bit word is the zero high-half of a value in [0,64). If int32, odd words
// are random values in [0,64): P(all zero over ntok/2 probes) ~ 64^-(ntok/2).
// ---------------------------------------------------------------------------
__global__ void detect_kernel(const int* __restrict__ op32, int ntok)
{
    __shared__ int any_nonzero;
    if (threadIdx.x == 0) any_nonzero = 0;
    __syncthreads();
    int nprobe = ntok / 2;          // safe under both int32 and int64 readings
    int nz = 0;
    for (int i = threadIdx.x; i < nprobe; i += blockDim.x)
        if (op32[2 * i + 1] != 0) nz = 1;
    if (nz) atomicOr(&any_nonzero, 1);
    __syncthreads();
    if (threadIdx.x == 0) g_is64 = any_nonzero ? 0 : 1;
}

// ---------------------------------------------------------------------------
// Kernel 0: inverse L2 norm of each expert key row (512 rows, 1 warp each)
// ---------------------------------------------------------------------------
__global__ __launch_bounds__(256) void key_norm_kernel(const float* __restrict__ key)
{
    int gw   = (blockIdx.x * blockDim.x + threadIdx.x) >> 5;
    int lane = threadIdx.x & 31;
    if (gw >= NB * EPB) return;
    const float4* kp = (const float4*)(key + (size_t)gw * EMBED);
    float ss = 0.f;
    #pragma unroll
    for (int c = 0; c < 8; c++) {
        float4 v = kp[c * 32 + lane];
        ss += v.x * v.x + v.y * v.y + v.z * v.z + v.w * v.w;
    }
    #pragma unroll
    for (int o = 16; o; o >>= 1) ss += __shfl_xor_sync(0xffffffffu, ss, o);
    if (lane == 0) g_key_rnorm[gw] = 1.0f / fmaxf(sqrtf(ss), 1e-12f);
}

// ---------------------------------------------------------------------------
// Kernel 1: router. One block per (bucket, slice). Keys (pre-normalized) live
// in smem; each warp processes 4 tokens per pass to amortize smem key reads.
// Output: float32 throughout. out[0:ntok*K]=gid (exact small ints as floats),
// out[ntok*K:2*ntok*K]=w.
// ---------------------------------------------------------------------------
__global__ __launch_bounds__(256) void router_kernel(
    const float* __restrict__ h,
    const void*  __restrict__ op_raw,
    const float* __restrict__ key,
    float*       __restrict__ out,
    int ntok)
{
    __shared__ float skey[EPB * EMBED];
    __shared__ int   slist[CAP];
    __shared__ int   scount;

    const int bucket = blockIdx.x / SPLIT;
    const int slice  = blockIdx.x % SPLIT;
    const int tid    = threadIdx.x;
    const int is64   = g_is64;

    if (tid == 0) scount = 0;

    // Stage keys * rnorm into smem (float4)
    const float4* kg = (const float4*)(key + (size_t)bucket * EPB * EMBED);
    float4*       ks = (float4*)skey;
    for (int i = tid; i < EPB * EMBED / 4; i += 256) {
        float  rn = g_key_rnorm[bucket * EPB + (i >> 8)];
        float4 v  = kg[i];
        v.x *= rn; v.y *= rn; v.z *= rn; v.w *= rn;
        ks[i] = v;
    }
    __syncthreads();

    // Scan this slice's op_ids, collect matching tokens
    const int cands = ntok / SPLIT;
    for (int j = tid; j < cands; j += 256) {
        int t = slice + j * SPLIT;
        long long v = is64 ? ((const long long*)op_raw)[t]
                           : (long long)((const int*)op_raw)[t];
        int b = (int)(v < 0 ? 0LL : (v > (NB - 1) ? (long long)(NB - 1) : v));
        if (b == bucket) {
            int p = atomicAdd(&scount, 1);
            if (p < CAP) slist[p] = t;
        }
    }
    __syncthreads();

    const int count = scount < CAP ? scount : CAP;
    const int wid   = tid >> 5;
    const int lane  = tid & 31;
    const int btk   = ntok * KTOP;          // float offset of the 'w' block
    const float4* h4p = (const float4*)h;

    for (int base = wid * 4; base < count; base += 8 * 4) {
        int  t[4];
        bool val[4];
        #pragma unroll
        for (int i = 0; i < 4; i++) {
            val[i] = (base + i) < count;
            t[i]   = val[i] ? slist[base + i] : slist[base];
        }

        float acc[4][EPB];
        float hh[4];
        #pragma unroll
        for (int i = 0; i < 4; i++) {
            hh[i] = 0.f;
            #pragma unroll
            for (int e = 0; e < EPB; e++) acc[i][e] = 0.f;
        }

        #pragma unroll
        for (int c = 0; c < 8; c++) {
            float4 hv[4];
            #pragma unroll
            for (int i = 0; i < 4; i++)
                hv[i] = h4p[(size_t)t[i] * (EMBED / 4) + c * 32 + lane];
            #pragma unroll
            for (int i = 0; i < 4; i++)
                hh[i] += hv[i].x * hv[i].x + hv[i].y * hv[i].y
                       + hv[i].z * hv[i].z + hv[i].w * hv[i].w;
            #pragma unroll
            for (int e = 0; e < EPB; e++) {
                float4 k4 = ks[e * (EMBED / 4) + c * 32 + lane];
                #pragma unroll
                for (int i = 0; i < 4; i++)
                    acc[i][e] += hv[i].x * k4.x + hv[i].y * k4.y
                               + hv[i].z * k4.z + hv[i].w * k4.w;
            }
        }

        // Butterfly all-reduce: every lane ends with full sums
        #pragma unroll
        for (int i = 0; i < 4; i++) {
            #pragma unroll
            for (int o = 16; o; o >>= 1) hh[i] += __shfl_xor_sync(0xffffffffu, hh[i], o);
            #pragma unroll
            for (int e = 0; e < EPB; e++) {
                #pragma unroll
                for (int o = 16; o; o >>= 1)
                    acc[i][e] += __shfl_xor_sync(0xffffffffu, acc[i][e], o);
            }
        }

        if (lane < 4 && val[lane]) {
            const int i  = lane;
            const int tt = t[i];
            float rh = 1.0f / fmaxf(sqrtf(hh[i]), 1e-12f);

            float p[EPB];
            float m = -1e30f;
            #pragma unroll
            for (int e = 0; e < EPB; e++) {
                p[e] = acc[i][e] * rh;      // TAU = 1.0
                m = fmaxf(m, p[e]);
            }
            float Z = 0.f;
            #pragma unroll
            for (int e = 0; e < EPB; e++) { p[e] = expf(p[e] - m); Z += p[e]; }

            // top-1 then top-2 (strict > => lowest index wins ties, like top_k)
            int   i1 = 0; float v1 = p[0];
            #pragma unroll
            for (int e = 1; e < EPB; e++) if (p[e] > v1) { v1 = p[e]; i1 = e; }
            int   i2 = -1; float v2 = -1.f;
            #pragma unroll
            for (int e = 0; e < EPB; e++)
                if (e != i1 && p[e] > v2) { v2 = p[e]; i2 = e; }

            v1 /= Z; v2 /= Z;
            float ws = v1 + v2 + 1e-9f;

            out[tt * 2 + 0]       = (float)(bucket * EPB + i1);
            out[tt * 2 + 1]       = (float)(bucket * EPB + i2);
            out[btk + tt * 2 + 0] = v1 / ws;
            out[btk + tt * 2 + 1] = v2 / ws;
        }
    }
}

// ---------------------------------------------------------------------------
extern "C" void kernel_launch(void* const* d_in, const int* in_sizes, int n_in,
                              void* d_out, int out_size)
{
    const float* h   = (const float*)d_in[0];
    const void*  op  = d_in[1];
    const float* key = (const float*)d_in[2];
    float*       out = (float*)d_out;
    int ntok = in_sizes[1];

    detect_kernel<<<1, 256>>>((const int*)op, ntok);
    key_norm_kernel<<<(NB * EPB * 32 + 255) / 256, 256>>>(key);
    router_kernel<<<NB * SPLIT, 256>>>(h, op, key, out, ntok);
}